// round 7
// baseline (speedup 1.0000x reference)
#include <cuda_runtime.h>
#include <cuda_bf16.h>
#include <cstdint>

// Problem constants (fixed by the dataset reference):
//   feature        [32,512,512] f32      -> P = 8,388,608 points
//   indices        [32,512,512,3] i32    -> 3P ints
//   feature_volume [256,256,256] f32     -> V = 16,777,216 voxels
//   count_volume   [256,256,256] f32
//   output: concat(feature_volume', count_volume') -> 2V f32
#define DIM     256
#define V_TOTAL (DIM * DIM * DIM)
#define V_HALF  (V_TOTAL / 2)

// Fused {sum, count} accumulator per voxel. Zeroed per-half by zero_kernel
// immediately before that half's scatter; finalize_half discards the lines
// from L2 after reading, so scratch data never reaches DRAM.
// 128B alignment: each 16-voxel group is exactly one L2 line (discard unit).
__device__ __align__(128) float2 g_scratch[V_TOTAL];

// Single 64-bit reduction: red.global.add.v2.f32 (sm_90+).
__device__ __forceinline__ void red_add_f32x2(float2* addr, float a, float b)
{
    asm volatile("red.global.add.v2.f32 [%0], {%1, %2};"
                 :: "l"(addr), "f"(a), "f"(b) : "memory");
}

// Invalidate one fully-owned, fully-consumed 128B line without writeback.
__device__ __forceinline__ void discard_line_l2(const void* p)
{
    asm volatile("discard.global.L2 [%0], 128;"
                 :: "l"(__cvta_generic_to_global(const_cast<void*>(p)))
                 : "memory");
}

// ---------------------------------------------------------------------------
// Zero one half of scratch. Warp-coalesced full-line stores write-allocate
// in L2 without DRAM fills and leave the lines resident+dirty for the REDs.
// ---------------------------------------------------------------------------
__global__ void __launch_bounds__(256) zero_kernel(int half)
{
    const int t = blockIdx.x * blockDim.x + threadIdx.x;
    float4* dst = reinterpret_cast<float4*>(g_scratch + (size_t)half * V_HALF);
    dst[t] = make_float4(0.f, 0.f, 0.f, 0.f);
}

// ---------------------------------------------------------------------------
// Scatter pass for one volume half (x>>7 == half): RMW working set is 67 MB,
// L2-resident. Inputs streamed with __ldcs (evict-first). One vector RED per
// in-half point.
// ---------------------------------------------------------------------------
__global__ void __launch_bounds__(256) scatter_kernel(
    const float* __restrict__ feat,
    const int*   __restrict__ idx,
    int P4, int half)
{
    int t = blockIdx.x * blockDim.x + threadIdx.x;
    if (t >= P4) return;

    const float4 f  = __ldcs(reinterpret_cast<const float4*>(feat) + t);
    const int4   i0 = __ldcs(reinterpret_cast<const int4*>(idx) + t * 3 + 0);
    const int4   i1 = __ldcs(reinterpret_cast<const int4*>(idx) + t * 3 + 1);
    const int4   i2 = __ldcs(reinterpret_cast<const int4*>(idx) + t * 3 + 2);

    const int xs[4] = { i0.x, i0.w, i1.z, i2.y };
    const int ys[4] = { i0.y, i1.x, i1.w, i2.z };
    const int zs[4] = { i0.z, i1.y, i2.x, i2.w };
    const float fv[4] = { f.x, f.y, f.z, f.w };

#pragma unroll
    for (int k = 0; k < 4; ++k) {
        const int x = xs[k], y = ys[k], z = zs[k];
        const bool valid = ((unsigned)x < (unsigned)DIM) &
                           ((unsigned)y < (unsigned)DIM) &
                           ((unsigned)z < (unsigned)DIM) &
                           ((x >> 7) == half);
        if (valid) {
            const int flat = (((x << 8) | y) << 8) | z;
            red_add_f32x2(&g_scratch[flat], fv[k], 1.0f);
        }
    }
}

// ---------------------------------------------------------------------------
// Finalize one half while its scratch is still L2-resident.
// Each thread owns 16 consecutive voxels = one 128B scratch line; after
// consuming it, the dirty line is discarded from L2 with NO writeback.
//   touched  : fv' = fv*cv + (sum/cnt)/(cv+1) ; cv' = cv+1
//   untouched: copy-through.
// ---------------------------------------------------------------------------
__global__ void __launch_bounds__(256) finalize_half_kernel(
    const float* __restrict__ fvol,
    const float* __restrict__ cvol,
    float*       __restrict__ out,
    int half)
{
    const int t = blockIdx.x * blockDim.x + threadIdx.x;   // 0 .. V_HALF/16-1
    const long base = (long)half * V_HALF + (long)t * 16;  // 16 voxels/thread

    const float4* scr = reinterpret_cast<const float4*>(g_scratch + base);
    const float4* fa4 = reinterpret_cast<const float4*>(fvol + base);
    const float4* ca4 = reinterpret_cast<const float4*>(cvol + base);
    float4* of4 = reinterpret_cast<float4*>(out + base);
    float4* oc4 = reinterpret_cast<float4*>(out + V_TOTAL + base);

#pragma unroll
    for (int g = 0; g < 4; ++g) {                  // 4 voxels per group
        const float4 s01 = scr[2 * g + 0];         // {sum0,cnt0,sum1,cnt1}
        const float4 s23 = scr[2 * g + 1];         // {sum2,cnt2,sum3,cnt3}
        const float4 a   = __ldcs(fa4 + g);
        const float4 c   = __ldcs(ca4 + g);

        const float sum[4] = { s01.x, s01.z, s23.x, s23.z };
        const float cnt[4] = { s01.y, s01.w, s23.y, s23.w };
        const float fa[4]  = { a.x, a.y, a.z, a.w };
        const float cc[4]  = { c.x, c.y, c.z, c.w };

        float of[4], oc[4];
#pragma unroll
        for (int k = 0; k < 4; ++k) {
            if (cnt[k] > 0.0f) {
                const float cn = cc[k] + 1.0f;
                of[k] = fa[k] * cc[k] + (sum[k] / cnt[k]) / cn;
                oc[k] = cn;
            } else {
                of[k] = fa[k];
                oc[k] = cc[k];
            }
        }

        __stcs(of4 + g, make_float4(of[0], of[1], of[2], of[3]));
        __stcs(oc4 + g, make_float4(oc[0], oc[1], oc[2], oc[3]));
    }

    // Drop this thread's (fully consumed, exclusively owned) dirty scratch
    // line from L2 without writeback. Re-zeroed by zero_kernel next replay
    // before any read, so determinism is preserved.
    discard_line_l2(g_scratch + base);
}

extern "C" void kernel_launch(void* const* d_in, const int* in_sizes, int n_in,
                              void* d_out, int out_size)
{
    const float* feat = (const float*)d_in[0];   // [P]
    const int*   idx  = (const int*)d_in[1];     // [P,3]
    const float* fvol = (const float*)d_in[2];   // [V]
    const float* cvol = (const float*)d_in[3];   // [V]
    float*       out  = (float*)d_out;           // [2V]

    const int P  = in_sizes[0];                  // 8,388,608 (divisible by 4)
    const int P4 = (P + 3) / 4;
    const int Z4 = V_HALF / 2;                   // float4 count per half
    const int F  = V_HALF / 16;                  // finalize threads per half

    for (int h = 0; h < 2; ++h) {
        zero_kernel<<<Z4 / 256, 256>>>(h);
        scatter_kernel<<<(P4 + 255) / 256, 256>>>(feat, idx, P4, h);
        finalize_half_kernel<<<F / 256, 256>>>(fvol, cvol, out, h);
    }
}